// round 6
// baseline (speedup 1.0000x reference)
#include <cuda_runtime.h>
#include <cuda_bf16.h>
#include <math.h>
#include <cstdint>

#define DM 128
#define NN 65536

// ---------------- device scratch (module globals; no runtime alloc) --------
__device__ float          g_c [NN * DM];     // cell state fp32
__device__ __nv_bfloat16  g_hh[NN * DM];     // h hi bf16, natural [node][k]
__device__ __nv_bfloat16  g_hl[NN * DM];     // h lo bf16 (h = hh + hl)
__device__ __nv_bfloat16  g_wth[640 * 256];  // W_bin^T hi [n][k] natural
__device__ __nv_bfloat16  g_wtl[640 * 256];  // W_bin^T lo

__device__ __forceinline__ float sigf(float x) { return 1.0f / (1.0f + expf(-x)); }

// mma.sync m16n8k16 bf16 -> f32 (tensor pipe; arch-neutral PTX)
#define MMA(acc, a, b0, b1)                                                     \
    asm volatile("mma.sync.aligned.m16n8k16.row.col.f32.bf16.bf16.f32 "         \
                 "{%0,%1,%2,%3}, {%4,%5,%6,%7}, {%8,%9}, {%0,%1,%2,%3};"        \
                 : "+f"((acc)[0]), "+f"((acc)[1]), "+f"((acc)[2]), "+f"((acc)[3]) \
                 : "r"((a)[0]), "r"((a)[1]), "r"((a)[2]), "r"((a)[3]),          \
                   "r"(b0), "r"(b1))

// B smem: 40 rows (5 gates x 8 dims) x 512B, stride 576 (64 mod 128 -> LDS.128
// conflict-free), hi block then lo block.
#define SBSTR  576
#define SBLO   (40 * SBSTR)            // 23040
#define SBTOT  (2 * 40 * SBSTR)        // 46080 (< 48KB static)

// ---------------------------------------------------------------------------
// prep: split + transpose W_bin [256,640] -> WT hi/lo [640,256] natural order
// ---------------------------------------------------------------------------
__global__ void prep_w(const float* __restrict__ Wb) {
    int i = blockIdx.x * 256 + threadIdx.x;   // 163840 total
    int k = i / 640, n = i % 640;
    float w = Wb[i];
    __nv_bfloat16 hi = __float2bfloat16(w);
    g_wth[n * 256 + k] = hi;
    g_wtl[n * 256 + k] = __float2bfloat16(w - __bfloat162float(hi));
}

// ---------------------------------------------------------------------------
// leaves: embed + norm clip, write h hi/lo, c=0, scatter output
// ---------------------------------------------------------------------------
__global__ void leaf_kernel(const int* __restrict__ tokens,
                            const float* __restrict__ emb,
                            float* __restrict__ out) {
    int n = blockIdx.x * 8 + (threadIdx.x >> 5);
    int lane = threadIdx.x & 31;
    int tok = tokens[n];
    float4 e = ((const float4*)emb)[tok * 32 + lane];
    float ss = e.x * e.x + e.y * e.y + e.z * e.z + e.w * e.w;
#pragma unroll
    for (int o = 16; o; o >>= 1) ss += __shfl_xor_sync(0xffffffffu, ss, o);
    float nrm = sqrtf(ss);
    float s = nrm > 1.0f ? 1.0f / nrm : 1.0f;
    float hv[4] = {e.x * s, e.y * s, e.z * s, e.w * s};
#pragma unroll
    for (int c = 0; c < 4; c++) {
        __nv_bfloat16 hi = __float2bfloat16(hv[c]);
        g_hh[n * DM + lane * 4 + c] = hi;
        g_hl[n * DM + lane * 4 + c] = __float2bfloat16(hv[c] - __bfloat162float(hi));
    }
    ((float4*)g_c)[n * 32 + lane] = make_float4(0.f, 0.f, 0.f, 0.f);
    int b = n >> 9, j = n & 511;
    ((float4*)out)[(b * 1024 + j) * 32 + lane] = make_float4(hv[0], hv[1], hv[2], hv[3]);
}

// ---------------------------------------------------------------------------
// binary level. Children of node m are rows (Gc+2m, Gc+2m+1) -> A matrix
// [128 x 256] bf16 is a CONTIGUOUS block at g_h? + (Gc+2*m0)*128 elems.
// CTA: 128 nodes x npass d-groups of (5 gates x 8 dims). 4 warps x 32 rows.
// 3-term bf16 split (hh + hl + lh), fp32 accum on tensor pipe.
// k is relabeled within each 32-elem block consistently for A and B so both
// fragments come from direct 16B loads (k-order of a dot product is free).
// ---------------------------------------------------------------------------
__global__ void __launch_bounds__(128)
bin_mma(const float* __restrict__ bb,
        int s, int Gc, int Mtot, int cshift, int offl, int npass,
        float* __restrict__ out) {
    __shared__ __align__(16) char sB[SBTOT];
    int t = threadIdx.x, wid = t >> 5, lane = t & 31;
    int g = lane >> 2, i = lane & 3;
    int m0 = blockIdx.x * 128;

    const char* Ah = (const char*)g_hh + (size_t)(Gc + 2 * m0) * 256;
    const char* Al = (const char*)g_hl + (size_t)(Gc + 2 * m0) * 256;

    // per-thread A row byte offsets: [rs][rowhalf]
    uint32_t abase[2][2];
#pragma unroll
    for (int rs = 0; rs < 2; rs++)
#pragma unroll
        for (int hf = 0; hf < 2; hf++)
            abase[rs][hf] = (uint32_t)(wid * 32 + rs * 16 + hf * 8 + g) * 512u
                          + (uint32_t)i * 16u;
    uint32_t bbase = (uint32_t)g * SBSTR + (uint32_t)i * 16u;

    for (int p = 0; p < npass; p++) {
        int dp = blockIdx.y * npass + p;        // d-group 0..15
        if (p) __syncthreads();
        // stage B hi/lo: smem row rr = q*8 + d  <-  WT row q*128 + dp*8 + d
#pragma unroll
        for (int it = 0; it < 10; it++) {
            int idx = it * 128 + t;             // 1280 uint4 per buffer
            int rr = idx >> 5, w = idx & 31;
            int grow = (rr >> 3) * 128 + dp * 8 + (rr & 7);
            *(uint4*)(sB + rr * SBSTR + w * 16) =
                *(const uint4*)(g_wth + grow * 256 + w * 8);
            *(uint4*)(sB + SBLO + rr * SBSTR + w * 16) =
                *(const uint4*)(g_wtl + grow * 256 + w * 8);
        }
        __syncthreads();

        float acc[5][2][4];
#pragma unroll
        for (int q = 0; q < 5; q++)
#pragma unroll
            for (int rs = 0; rs < 2; rs++)
#pragma unroll
                for (int c = 0; c < 4; c++) acc[q][rs][c] = 0.f;

        // k loop: 8 pairs of k16-chunks (64B per row each pair)
#pragma unroll
        for (int pr = 0; pr < 8; pr++) {
            uint4 uh[2][2], ul[2][2];
#pragma unroll
            for (int rs = 0; rs < 2; rs++)
#pragma unroll
                for (int hf = 0; hf < 2; hf++) {
                    uint32_t off = abase[rs][hf] + (uint32_t)pr * 64u;
                    uh[rs][hf] = *(const uint4*)(Ah + off);
                    ul[rs][hf] = *(const uint4*)(Al + off);
                }
#pragma unroll
            for (int q = 0; q < 5; q++) {
                uint32_t boff = bbase + (uint32_t)q * (8 * SBSTR) + (uint32_t)pr * 64u;
                uint4 bh = *(const uint4*)(sB + boff);
                uint4 bl = *(const uint4*)(sB + SBLO + boff);
#pragma unroll
                for (int rs = 0; rs < 2; rs++) {
                    uint32_t a0[4] = {uh[rs][0].x, uh[rs][1].x, uh[rs][0].y, uh[rs][1].y};
                    uint32_t l0[4] = {ul[rs][0].x, ul[rs][1].x, ul[rs][0].y, ul[rs][1].y};
                    MMA(acc[q][rs], a0, bh.x, bh.y);
                    MMA(acc[q][rs], a0, bl.x, bl.y);
                    MMA(acc[q][rs], l0, bh.x, bh.y);
                    uint32_t a1[4] = {uh[rs][0].z, uh[rs][1].z, uh[rs][0].w, uh[rs][1].w};
                    uint32_t l1[4] = {ul[rs][0].z, ul[rs][1].z, ul[rs][0].w, ul[rs][1].w};
                    MMA(acc[q][rs], a1, bh.z, bh.w);
                    MMA(acc[q][rs], a1, bl.z, bl.w);
                    MMA(acc[q][rs], l1, bh.z, bh.w);
                }
            }
        }

        // epilogue for this d-group
#pragma unroll
        for (int rs = 0; rs < 2; rs++) {
#pragma unroll
            for (int gg = 0; gg < 2; gg++) {
                int lm = wid * 32 + rs * 16 + gg * 8 + g;
                if (m0 + lm >= Mtot) continue;
                int node = s + m0 + lm;
                int ch = Gc + 2 * (m0 + lm);
                int dd = dp * 8 + i * 2;
                float2 cl = *(const float2*)(g_c + (size_t)ch * DM + dd);
                float2 cr = *(const float2*)(g_c + (size_t)(ch + 1) * DM + dd);
                float hv[2], cv[2];
#pragma unroll
                for (int e = 0; e < 2; e++) {
                    float gi = acc[0][rs][gg * 2 + e] + bb[0 * 128 + dd + e];
                    float go = acc[1][rs][gg * 2 + e] + bb[1 * 128 + dd + e];
                    float gu = acc[2][rs][gg * 2 + e] + bb[2 * 128 + dd + e];
                    float gl = acc[3][rs][gg * 2 + e] + bb[3 * 128 + dd + e];
                    float gr = acc[4][rs][gg * 2 + e] + bb[4 * 128 + dd + e];
                    float clv = e ? cl.y : cl.x;
                    float crv = e ? cr.y : cr.x;
                    float c = sigf(gi) * tanhf(gu) + sigf(gl) * clv + sigf(gr) * crv;
                    cv[e] = c;
                    hv[e] = sigf(go) * tanhf(c);
                }
                *(float2*)(g_c + (size_t)node * DM + dd) = make_float2(cv[0], cv[1]);
                __nv_bfloat16 h0 = __float2bfloat16(hv[0]);
                __nv_bfloat16 h1 = __float2bfloat16(hv[1]);
                __nv_bfloat162 hhp; hhp.x = h0; hhp.y = h1;
                __nv_bfloat162 hlp;
                hlp.x = __float2bfloat16(hv[0] - __bfloat162float(h0));
                hlp.y = __float2bfloat16(hv[1] - __bfloat162float(h1));
                *(__nv_bfloat162*)(g_hh + (size_t)node * DM + dd) = hhp;
                *(__nv_bfloat162*)(g_hl + (size_t)node * DM + dd) = hlp;
                int local = m0 + lm;
                int b = local >> cshift;
                int jj = local & ((1 << cshift) - 1);
                *(float2*)(out + ((size_t)(b * 1024 + offl + jj)) * DM + dd) =
                    make_float2(hv[0], hv[1]);
            }
        }
    }
}

// ---------------------------------------------------------------------------
// unary top level: 64 nodes, child = 65408 + b (contiguous), K=128, N=512
// ---------------------------------------------------------------------------
__global__ void unary_kernel(const float* __restrict__ Wu,
                             const float* __restrict__ bu,
                             float* __restrict__ out) {
    __shared__ float xh[128];
    int tx = threadIdx.x;
    int ch = 65408 + blockIdx.x;
    xh[tx] = __bfloat162float(g_hh[ch * DM + tx]) + __bfloat162float(g_hl[ch * DM + tx]);
    __syncthreads();
    float acc[4] = {0.f, 0.f, 0.f, 0.f};
    for (int k = 0; k < 128; k++) {
        float x = xh[k];
#pragma unroll
        for (int q = 0; q < 4; q++) acc[q] += x * Wu[k * 512 + q * 128 + tx];
    }
    float cc = g_c[ch * DM + tx];
    float gi = acc[0] + bu[tx];
    float go = acc[1] + bu[128 + tx];
    float gu = acc[2] + bu[256 + tx];
    float gf = acc[3] + bu[384 + tx];
    float c = sigf(gi) * tanhf(gu) + sigf(gf) * cc;
    float h = sigf(go) * tanhf(c);
    out[((size_t)(blockIdx.x * 1024 + 1023)) * DM + tx] = h;
}

// ---------------------------------------------------------------------------
// kernel_launch: ONLY kernel launches (graph-capturable)
// ---------------------------------------------------------------------------
extern "C" void kernel_launch(void* const* d_in, const int* in_sizes, int n_in,
                              void* d_out, int out_size) {
    const int* tokens = (const int*)d_in[0];
    const float* emb  = (const float*)d_in[3];
    const float* Wu   = (const float*)d_in[4];
    const float* bu   = (const float*)d_in[5];
    const float* Wb   = (const float*)d_in[6];
    const float* bb   = (const float*)d_in[7];
    float* out = (float*)d_out;

    static const int Gh[10]  = {0, 32768, 49152, 57344, 61440, 63488,
                                64512, 65024, 65280, 65408};
    static const int Csh[10] = {9, 8, 7, 6, 5, 4, 3, 2, 1, 0};     // log2(C[l])
    static const int Off[10] = {0, 512, 768, 896, 960, 992, 1008, 1016, 1020, 1022};
    // passes per CTA over the 16 d-groups: big levels amortize A traffic,
    // small levels maximize CTA count (latency).
    static const int Np[10]  = {0, 4, 4, 2, 1, 1, 1, 1, 1, 1};

    prep_w<<<640, 256>>>(Wb);
    leaf_kernel<<<4096, 256>>>(tokens, emb, out);
    for (int l = 1; l <= 9; l++) {
        int M = 32768 >> l;                    // nodes this level (level 9 -> 64)
        dim3 grid((M + 127) / 128, 16 / Np[l]);
        bin_mma<<<grid, 128>>>(bb, Gh[l], Gh[l - 1], M, Csh[l], Off[l], Np[l], out);
    }
    unary_kernel<<<64, 128>>>(Wu, bu, out);
}

// round 7
// speedup vs baseline: 2.1067x; 2.1067x over previous
#include <cuda_runtime.h>
#include <cuda_fp16.h>
#include <math.h>
#include <cstdint>

#define DM 128
#define NN 65536

// ---------------- device scratch (module globals; no runtime alloc) --------
__device__ float  g_c[NN * DM];      // cell state fp32
__device__ __half g_h[NN * DM];      // hidden state fp16, natural [node][k]
__device__ __half g_wt[640 * 256];   // W_bin^T fp16 [n][k]

__device__ __forceinline__ float sigf(float x) { return 1.0f / (1.0f + expf(-x)); }

// mma.sync m16n8k16 fp16 -> f32 (tensor pipe; arch-neutral PTX)
#define MMA(acc, a, b0, b1)                                                     \
    asm volatile("mma.sync.aligned.m16n8k16.row.col.f32.f16.f16.f32 "           \
                 "{%0,%1,%2,%3}, {%4,%5,%6,%7}, {%8,%9}, {%0,%1,%2,%3};"        \
                 : "+f"((acc)[0]), "+f"((acc)[1]), "+f"((acc)[2]), "+f"((acc)[3]) \
                 : "r"((a)[0]), "r"((a)[1]), "r"((a)[2]), "r"((a)[3]),          \
                   "r"(b0), "r"(b1))

// B smem: 80 rows (5 gates x 16 dims) x 512B, stride 576 (conflict-free LDS.128)
#define SBSTR 576
#define SBTOT (80 * SBSTR)   // 46080 B static (< 48KB)

// ---------------------------------------------------------------------------
// prep: transpose W_bin [256,640] -> WT fp16 [640,256]
// ---------------------------------------------------------------------------
__global__ void prep_w(const float* __restrict__ Wb) {
    int i = blockIdx.x * 256 + threadIdx.x;   // 163840 total
    int k = i / 640, n = i % 640;
    g_wt[n * 256 + k] = __float2half(Wb[i]);
}

// ---------------------------------------------------------------------------
// leaves: embed + norm clip, write h fp16, c=0, scatter output
// ---------------------------------------------------------------------------
__global__ void leaf_kernel(const int* __restrict__ tokens,
                            const float* __restrict__ emb,
                            float* __restrict__ out) {
    int n = blockIdx.x * 8 + (threadIdx.x >> 5);
    int lane = threadIdx.x & 31;
    int tok = tokens[n];
    float4 e = ((const float4*)emb)[tok * 32 + lane];
    float ss = e.x * e.x + e.y * e.y + e.z * e.z + e.w * e.w;
#pragma unroll
    for (int o = 16; o; o >>= 1) ss += __shfl_xor_sync(0xffffffffu, ss, o);
    float nrm = sqrtf(ss);
    float s = nrm > 1.0f ? 1.0f / nrm : 1.0f;
    float hv[4] = {e.x * s, e.y * s, e.z * s, e.w * s};
    __half2* hp = (__half2*)(g_h + n * DM + lane * 4);
    hp[0] = __floats2half2_rn(hv[0], hv[1]);
    hp[1] = __floats2half2_rn(hv[2], hv[3]);
    ((float4*)g_c)[n * 32 + lane] = make_float4(0.f, 0.f, 0.f, 0.f);
    int b = n >> 9, j = n & 511;
    ((float4*)out)[(b * 1024 + j) * 32 + lane] = make_float4(hv[0], hv[1], hv[2], hv[3]);
}

// ---------------------------------------------------------------------------
// binary level. Children of node m are rows (Gc+2m, Gc+2m+1), so the A matrix
// [128 x 256] fp16 is a contiguous block at g_h + (Gc+2*m0)*128.
// CTA: 256 thr = 8 warps x 16 rows. N-tile = 80 (5 gates x 16 dims), K=256.
// Single fp16 MMA pass, fp32 accumulate. k relabeled identically in A and B
// fragments so all operands come from direct 16B loads.
// ---------------------------------------------------------------------------
__global__ void __launch_bounds__(256)
bin_mma(const float* __restrict__ bb,
        int s, int Gc, int Mtot, int cshift, int offl, int npass,
        float* __restrict__ out) {
    __shared__ __align__(16) char sB[SBTOT];
    int t = threadIdx.x, wid = t >> 5, lane = t & 31;
    int g = lane >> 2, i = lane & 3;
    int m0 = blockIdx.x * 128;

    const char* A = (const char*)g_h + (size_t)(Gc + 2 * m0) * 256;  // bytes
    uint32_t arow0 = (uint32_t)(wid * 16 + g) * 512u + (uint32_t)i * 16u;
    uint32_t arow1 = arow0 + 8u * 512u;

    for (int p = 0; p < npass; p++) {
        int dp = blockIdx.y * npass + p;      // d-group 0..7 (16 dims each)
        if (p) __syncthreads();
        // stage B: smem row rr = q*16 + d  <-  WT row q*128 + dp*16 + d
#pragma unroll
        for (int it = 0; it < 10; it++) {
            int idx = it * 256 + t;           // 2560 uint4
            int rr = idx >> 5, w = idx & 31;
            int grow = (rr >> 4) * 128 + dp * 16 + (rr & 15);
            *(uint4*)(sB + rr * SBSTR + w * 16) =
                *(const uint4*)(g_wt + grow * 256 + w * 8);
        }
        __syncthreads();

        float acc[5][2][4];
#pragma unroll
        for (int q = 0; q < 5; q++)
#pragma unroll
            for (int dh = 0; dh < 2; dh++)
#pragma unroll
                for (int c = 0; c < 4; c++) acc[q][dh][c] = 0.f;

#pragma unroll
        for (int pr = 0; pr < 8; pr++) {
            uint4 a0 = *(const uint4*)(A + arow0 + (uint32_t)pr * 64u);
            uint4 a1 = *(const uint4*)(A + arow1 + (uint32_t)pr * 64u);
            uint32_t f0[4] = {a0.x, a1.x, a0.y, a1.y};
            uint32_t f1[4] = {a0.z, a1.z, a0.w, a1.w};
#pragma unroll
            for (int q = 0; q < 5; q++) {
#pragma unroll
                for (int dh = 0; dh < 2; dh++) {
                    uint4 b = *(const uint4*)(sB + (q * 16 + dh * 8 + g) * SBSTR
                                              + i * 16 + pr * 64);
                    MMA(acc[q][dh], f0, b.x, b.y);
                    MMA(acc[q][dh], f1, b.z, b.w);
                }
            }
        }

        // ---- epilogue: thread covers rows {g, g+8} x dims {dh*8 + 2i, +1}
#pragma unroll
        for (int rh = 0; rh < 2; rh++) {
            int lm = wid * 16 + rh * 8 + g;
            if (m0 + lm >= Mtot) continue;
            int node = s + m0 + lm;
            int ch = Gc + 2 * (m0 + lm);
            int local = m0 + lm;
            int b = local >> cshift;
            int jj = local & ((1 << cshift) - 1);
            size_t orow = ((size_t)(b * 1024 + offl + jj)) * DM;
#pragma unroll
            for (int dh = 0; dh < 2; dh++) {
                int dd = dp * 16 + dh * 8 + i * 2;
                float2 cl = *(const float2*)(g_c + (size_t)ch * DM + dd);
                float2 cr = *(const float2*)(g_c + (size_t)(ch + 1) * DM + dd);
                float hv[2], cv[2];
#pragma unroll
                for (int e = 0; e < 2; e++) {
                    float gi = acc[0][dh][rh * 2 + e] + bb[0 * 128 + dd + e];
                    float go = acc[1][dh][rh * 2 + e] + bb[1 * 128 + dd + e];
                    float gu = acc[2][dh][rh * 2 + e] + bb[2 * 128 + dd + e];
                    float gl = acc[3][dh][rh * 2 + e] + bb[3 * 128 + dd + e];
                    float gr = acc[4][dh][rh * 2 + e] + bb[4 * 128 + dd + e];
                    float clv = e ? cl.y : cl.x;
                    float crv = e ? cr.y : cr.x;
                    float c = sigf(gi) * tanhf(gu) + sigf(gl) * clv + sigf(gr) * crv;
                    cv[e] = c;
                    hv[e] = sigf(go) * tanhf(c);
                }
                *(float2*)(g_c + (size_t)node * DM + dd) = make_float2(cv[0], cv[1]);
                *(__half2*)(g_h + (size_t)node * DM + dd) =
                    __floats2half2_rn(hv[0], hv[1]);
                *(float2*)(out + orow + dd) = make_float2(hv[0], hv[1]);
            }
        }
    }
}

// ---------------------------------------------------------------------------
// unary top level: 64 nodes, child = 65408 + b (contiguous), K=128, N=512
// ---------------------------------------------------------------------------
__global__ void unary_kernel(const float* __restrict__ Wu,
                             const float* __restrict__ bu,
                             float* __restrict__ out) {
    __shared__ float xh[128];
    int tx = threadIdx.x;
    int ch = 65408 + blockIdx.x;
    xh[tx] = __half2float(g_h[ch * DM + tx]);
    __syncthreads();
    float acc[4] = {0.f, 0.f, 0.f, 0.f};
    for (int k = 0; k < 128; k++) {
        float x = xh[k];
#pragma unroll
        for (int q = 0; q < 4; q++) acc[q] += x * Wu[k * 512 + q * 128 + tx];
    }
    float cc = g_c[ch * DM + tx];
    float gi = acc[0] + bu[tx];
    float go = acc[1] + bu[128 + tx];
    float gu = acc[2] + bu[256 + tx];
    float gf = acc[3] + bu[384 + tx];
    float c = sigf(gi) * tanhf(gu) + sigf(gf) * cc;
    float h = sigf(go) * tanhf(c);
    out[((size_t)(blockIdx.x * 1024 + 1023)) * DM + tx] = h;
}

// ---------------------------------------------------------------------------
// kernel_launch: ONLY kernel launches (graph-capturable)
// ---------------------------------------------------------------------------
extern "C" void kernel_launch(void* const* d_in, const int* in_sizes, int n_in,
                              void* d_out, int out_size) {
    const int* tokens = (const int*)d_in[0];
    const float* emb  = (const float*)d_in[3];
    const float* Wu   = (const float*)d_in[4];
    const float* bu   = (const float*)d_in[5];
    const float* Wb   = (const float*)d_in[6];
    const float* bb   = (const float*)d_in[7];
    float* out = (float*)d_out;

    static const int Gh[10]  = {0, 32768, 49152, 57344, 61440, 63488,
                                64512, 65024, 65280, 65408};
    static const int Csh[10] = {9, 8, 7, 6, 5, 4, 3, 2, 1, 0};     // log2(C[l])
    static const int Off[10] = {0, 512, 768, 896, 960, 992, 1008, 1016, 1020, 1022};
    // passes over the 8 d-groups: big levels amortize A reads, small levels
    // keep max CTA-parallelism.
    static const int Np[10]  = {0, 2, 2, 1, 1, 1, 1, 1, 1, 1};

    prep_w<<<640, 256>>>(Wb);
    leaf_kernel<<<4096, 256>>>(tokens, emb, out);
    for (int l = 1; l <= 9; l++) {
        int M = 32768 >> l;                   // nodes this level (level 9 -> 64)
        dim3 grid((M + 127) / 128, 8 / Np[l]);
        bin_mma<<<grid, 256>>>(bb, Gh[l], Gh[l - 1], M, Csh[l], Off[l], Np[l], out);
    }
    unary_kernel<<<64, 128>>>(Wu, bu, out);
}

// round 8
// speedup vs baseline: 2.2912x; 1.0876x over previous
#include <cuda_runtime.h>
#include <cuda_fp16.h>
#include <math.h>
#include <cstdint>

#define DM 128
#define NN 65536

// ---------------- device scratch (module globals; no runtime alloc) --------
__device__ float  g_c[NN * DM];      // cell state fp32 (leaves implicit zero)
__device__ __half g_h[NN * DM];      // hidden state fp16, natural [node][k]
__device__ __half g_wt[640 * 256];   // W_bin^T fp16 [n][k]

__device__ __forceinline__ float sigf(float x) { return 1.0f / (1.0f + expf(-x)); }

// mma.sync m16n8k16 fp16 -> f32 (tensor pipe; arch-neutral PTX)
#define MMA(acc, a, b0, b1)                                                     \
    asm volatile("mma.sync.aligned.m16n8k16.row.col.f32.f16.f16.f32 "           \
                 "{%0,%1,%2,%3}, {%4,%5,%6,%7}, {%8,%9}, {%0,%1,%2,%3};"        \
                 : "+f"((acc)[0]), "+f"((acc)[1]), "+f"((acc)[2]), "+f"((acc)[3]) \
                 : "r"((a)[0]), "r"((a)[1]), "r"((a)[2]), "r"((a)[3]),          \
                   "r"(b0), "r"(b1))

// B smem: 80 rows (5 gates x 16 dims) x 512B, stride 576 (conflict-free LDS.128)
#define SBSTR 576
#define SBTOT (80 * SBSTR)   // 46080 B static (< 48KB)

// ---------------------------------------------------------------------------
// prep: transpose W_bin [256,640] -> WT fp16 [640,256]
// ---------------------------------------------------------------------------
__global__ void prep_w(const float* __restrict__ Wb) {
    int i = blockIdx.x * 256 + threadIdx.x;   // 163840 total
    int k = i / 640, n = i % 640;
    g_wt[n * 256 + k] = __float2half(Wb[i]);
}

// ---------------------------------------------------------------------------
// leaves: embed + norm clip, write h fp16, scatter output. (c of leaves is
// identically zero -> never materialized; level 1 uses czero flag.)
// ---------------------------------------------------------------------------
__global__ void leaf_kernel(const int* __restrict__ tokens,
                            const float* __restrict__ emb,
                            float* __restrict__ out) {
    int n = blockIdx.x * 8 + (threadIdx.x >> 5);
    int lane = threadIdx.x & 31;
    int tok = tokens[n];
    float4 e = ((const float4*)emb)[tok * 32 + lane];
    float ss = e.x * e.x + e.y * e.y + e.z * e.z + e.w * e.w;
#pragma unroll
    for (int o = 16; o; o >>= 1) ss += __shfl_xor_sync(0xffffffffu, ss, o);
    float nrm = sqrtf(ss);
    float s = nrm > 1.0f ? 1.0f / nrm : 1.0f;
    float hv[4] = {e.x * s, e.y * s, e.z * s, e.w * s};
    __half2* hp = (__half2*)(g_h + n * DM + lane * 4);
    hp[0] = __floats2half2_rn(hv[0], hv[1]);
    hp[1] = __floats2half2_rn(hv[2], hv[3]);
    int b = n >> 9, j = n & 511;
    ((float4*)out)[(b * 1024 + j) * 32 + lane] = make_float4(hv[0], hv[1], hv[2], hv[3]);
}

// ---------------------------------------------------------------------------
// binary level. Children of node m are rows (Gc+2m, Gc+2m+1), so the A matrix
// [128 x 256] fp16 is a contiguous block at g_h + (Gc+2*m0)*128.
// CTA: 256 thr = 8 warps x 16 rows; N-tile = 80 (5 gates x 16 dims), K=256.
// grid.y = 8 d-groups. Single fp16 MMA pass, fp32 accumulate.
// __launch_bounds__(256,3): cap regs so 3 CTAs (24 warps) fit per SM.
// ---------------------------------------------------------------------------
__global__ void __launch_bounds__(256, 3)
bin_mma(const float* __restrict__ bb,
        int s, int Gc, int Mtot, int cshift, int offl, int czero,
        float* __restrict__ out) {
    __shared__ __align__(16) char sB[SBTOT];
    int t = threadIdx.x, wid = t >> 5, lane = t & 31;
    int g = lane >> 2, i = lane & 3;
    int m0 = blockIdx.x * 128;
    int dp = blockIdx.y;                      // d-group 0..7 (16 dims each)

    const char* A = (const char*)g_h + (size_t)(Gc + 2 * m0) * 256;  // bytes
    uint32_t arow = (uint32_t)(wid * 16 + g) * 512u + (uint32_t)i * 16u;

    // stage B: smem row rr = q*16 + d  <-  WT row q*128 + dp*16 + d
#pragma unroll
    for (int it = 0; it < 10; it++) {
        int idx = it * 256 + t;               // 2560 uint4
        int rr = idx >> 5, w = idx & 31;
        int grow = (rr >> 4) * 128 + dp * 16 + (rr & 15);
        *(uint4*)(sB + rr * SBSTR + w * 16) =
            *(const uint4*)(g_wt + grow * 256 + w * 8);
    }
    __syncthreads();

    float acc[5][2][4];
#pragma unroll
    for (int q = 0; q < 5; q++)
#pragma unroll
        for (int dh = 0; dh < 2; dh++)
#pragma unroll
            for (int c = 0; c < 4; c++) acc[q][dh][c] = 0.f;

#pragma unroll
    for (int pr = 0; pr < 8; pr++) {
        uint4 a0 = *(const uint4*)(A + arow + (uint32_t)pr * 64u);
        uint4 a1 = *(const uint4*)(A + arow + 8u * 512u + (uint32_t)pr * 64u);
        uint32_t f0[4] = {a0.x, a1.x, a0.y, a1.y};
        uint32_t f1[4] = {a0.z, a1.z, a0.w, a1.w};
#pragma unroll
        for (int q = 0; q < 5; q++) {
#pragma unroll
            for (int dh = 0; dh < 2; dh++) {
                uint4 b = *(const uint4*)(sB + (q * 16 + dh * 8 + g) * SBSTR
                                          + i * 16 + pr * 64);
                MMA(acc[q][dh], f0, b.x, b.y);
                MMA(acc[q][dh], f1, b.z, b.w);
            }
        }
    }

    // ---- epilogue: thread covers rows {g, g+8} x dims {dh*8 + 2i, +1}
#pragma unroll
    for (int rh = 0; rh < 2; rh++) {
        int lm = wid * 16 + rh * 8 + g;
        if (m0 + lm >= Mtot) continue;
        int node = s + m0 + lm;
        int ch = Gc + 2 * (m0 + lm);
        int local = m0 + lm;
        int b = local >> cshift;
        int jj = local & ((1 << cshift) - 1);
        size_t orow = ((size_t)(b * 1024 + offl + jj)) * DM;
#pragma unroll
        for (int dh = 0; dh < 2; dh++) {
            int dd = dp * 16 + dh * 8 + i * 2;
            float2 cl = make_float2(0.f, 0.f), cr = make_float2(0.f, 0.f);
            if (!czero) {
                cl = *(const float2*)(g_c + (size_t)ch * DM + dd);
                cr = *(const float2*)(g_c + (size_t)(ch + 1) * DM + dd);
            }
            float hv[2], cv[2];
#pragma unroll
            for (int e = 0; e < 2; e++) {
                float gi = acc[0][dh][rh * 2 + e] + bb[0 * 128 + dd + e];
                float go = acc[1][dh][rh * 2 + e] + bb[1 * 128 + dd + e];
                float gu = acc[2][dh][rh * 2 + e] + bb[2 * 128 + dd + e];
                float gl = acc[3][dh][rh * 2 + e] + bb[3 * 128 + dd + e];
                float gr = acc[4][dh][rh * 2 + e] + bb[4 * 128 + dd + e];
                float clv = e ? cl.y : cl.x;
                float crv = e ? cr.y : cr.x;
                float c = sigf(gi) * tanhf(gu) + sigf(gl) * clv + sigf(gr) * crv;
                cv[e] = c;
                hv[e] = sigf(go) * tanhf(c);
            }
            *(float2*)(g_c + (size_t)node * DM + dd) = make_float2(cv[0], cv[1]);
            *(__half2*)(g_h + (size_t)node * DM + dd) =
                __floats2half2_rn(hv[0], hv[1]);
            *(float2*)(out + orow + dd) = make_float2(hv[0], hv[1]);
        }
    }
}

// ---------------------------------------------------------------------------
// unary top level: 64 nodes, child = 65408 + b (contiguous), K=128, N=512
// ---------------------------------------------------------------------------
__global__ void unary_kernel(const float* __restrict__ Wu,
                             const float* __restrict__ bu,
                             float* __restrict__ out) {
    __shared__ float xh[128];
    int tx = threadIdx.x;
    int ch = 65408 + blockIdx.x;
    xh[tx] = __half2float(g_h[ch * DM + tx]);
    __syncthreads();
    float acc[4] = {0.f, 0.f, 0.f, 0.f};
    for (int k = 0; k < 128; k++) {
        float x = xh[k];
#pragma unroll
        for (int q = 0; q < 4; q++) acc[q] += x * Wu[k * 512 + q * 128 + tx];
    }
    float cc = g_c[ch * DM + tx];
    float gi = acc[0] + bu[tx];
    float go = acc[1] + bu[128 + tx];
    float gu = acc[2] + bu[256 + tx];
    float gf = acc[3] + bu[384 + tx];
    float c = sigf(gi) * tanhf(gu) + sigf(gf) * cc;
    float h = sigf(go) * tanhf(c);
    out[((size_t)(blockIdx.x * 1024 + 1023)) * DM + tx] = h;
}

// ---------------------------------------------------------------------------
// kernel_launch: ONLY kernel launches (graph-capturable)
// ---------------------------------------------------------------------------
extern "C" void kernel_launch(void* const* d_in, const int* in_sizes, int n_in,
                              void* d_out, int out_size) {
    const int* tokens = (const int*)d_in[0];
    const float* emb  = (const float*)d_in[3];
    const float* Wu   = (const float*)d_in[4];
    const float* bu   = (const float*)d_in[5];
    const float* Wb   = (const float*)d_in[6];
    const float* bb   = (const float*)d_in[7];
    float* out = (float*)d_out;

    static const int Gh[10]  = {0, 32768, 49152, 57344, 61440, 63488,
                                64512, 65024, 65280, 65408};
    static const int Csh[10] = {9, 8, 7, 6, 5, 4, 3, 2, 1, 0};     // log2(C[l])
    static const int Off[10] = {0, 512, 768, 896, 960, 992, 1008, 1016, 1020, 1022};

    prep_w<<<640, 256>>>(Wb);
    leaf_kernel<<<4096, 256>>>(tokens, emb, out);
    for (int l = 1; l <= 9; l++) {
        int M = 32768 >> l;                   // nodes this level (level 9 -> 64)
        dim3 grid((M + 127) / 128, 8);
        bin_mma<<<grid, 256>>>(bb, Gh[l], Gh[l - 1], M, Csh[l], Off[l],
                               (l == 1) ? 1 : 0, out);
    }
    unary_kernel<<<64, 128>>>(Wu, bu, out);
}

// round 9
// speedup vs baseline: 2.3670x; 1.0331x over previous
#include <cuda_runtime.h>
#include <cuda_fp16.h>
#include <math.h>
#include <cstdint>

#define DM 128
#define NN 65536
#define NC 296          // persistent grid: 2 CTAs/SM x 148 SMs (co-resident guaranteed)

// ---------------- device scratch (module globals; no runtime alloc) --------
__device__ float    g_c[NN * DM];              // cell state fp32 (leaf c implicit 0)
__device__ __half   g_h[(NN + 256) * DM];      // hidden fp16; +256 rows pad (tile overread)
__device__ __half   g_wt[640 * 256];           // W_bin^T fp16 [n][k]
__device__ unsigned g_cnt[16];                 // grid barrier arrival counters
__device__ unsigned g_gen[16];                 // grid barrier generations (monotonic)

__device__ __forceinline__ float sigf(float x) { return 1.0f / (1.0f + expf(-x)); }

// mma.sync m16n8k16 fp16 -> f32 (tensor pipe; arch-neutral PTX)
#define MMA(acc, a, b0, b1)                                                     \
    asm volatile("mma.sync.aligned.m16n8k16.row.col.f32.f16.f16.f32 "           \
                 "{%0,%1,%2,%3}, {%4,%5,%6,%7}, {%8,%9}, {%0,%1,%2,%3};"        \
                 : "+f"((acc)[0]), "+f"((acc)[1]), "+f"((acc)[2]), "+f"((acc)[3]) \
                 : "r"((a)[0]), "r"((a)[1]), "r"((a)[2]), "r"((a)[3]),          \
                   "r"(b0), "r"(b1))

// B smem: 80 rows (5 gates x 16 dims) x 512B, stride 576 (conflict-free LDS.128)
#define SBSTR 576
#define SBTOT (80 * SBSTR)   // 46080 B static

// grid-wide barrier: generation counting, replay-safe (gen monotonic across launches)
__device__ __forceinline__ void grid_bar(int b) {
    __syncthreads();
    if (threadIdx.x == 0) {
        __threadfence();
        unsigned my = ((volatile unsigned*)g_gen)[b];
        unsigned old = atomicAdd(&g_cnt[b], 1u);
        if (old == (unsigned)(NC - 1)) {
            g_cnt[b] = 0;                       // all arrived; safe to reset
            __threadfence();
            atomicAdd(&g_gen[b], 1u);
        } else {
            while (((volatile unsigned*)g_gen)[b] == my) __nanosleep(64);
        }
        __threadfence();
    }
    __syncthreads();
}

// ---------------------------------------------------------------------------
// ONE persistent kernel: prep W + leaves | bar | 9 binary levels (bar between)
// | unary top. Saves 11 launch boundaries + per-launch L1 flushes.
// ---------------------------------------------------------------------------
__global__ void __launch_bounds__(256, 2)
fused(const int* __restrict__ tokens, const float* __restrict__ emb,
      const float* __restrict__ Wu, const float* __restrict__ bu,
      const float* __restrict__ Wb, const float* __restrict__ bbin,
      float* __restrict__ out) {
    __shared__ __align__(16) char sB[SBTOT];
    int t = threadIdx.x, cta = blockIdx.x;
    int wid = t >> 5, lane = t & 31;
    int g = lane >> 2, i = lane & 3;

    // ---- phase 0a: W_bin [256,640] -> WT fp16 [640,256]
    for (int idx = cta * 256 + t; idx < 256 * 640; idx += NC * 256) {
        int k = idx / 640, n = idx % 640;
        g_wt[n * 256 + k] = __float2half(Wb[idx]);
    }
    // ---- phase 0b: leaves (one warp per node): embed + norm clip
    for (int n = cta * 8 + wid; n < 32768; n += NC * 8) {
        int tok = tokens[n];
        float4 e = ((const float4*)emb)[tok * 32 + lane];
        float ss = e.x * e.x + e.y * e.y + e.z * e.z + e.w * e.w;
#pragma unroll
        for (int o = 16; o; o >>= 1) ss += __shfl_xor_sync(0xffffffffu, ss, o);
        float nrm = sqrtf(ss);
        float sc = nrm > 1.0f ? 1.0f / nrm : 1.0f;
        float hv[4] = {e.x * sc, e.y * sc, e.z * sc, e.w * sc};
        __half2* hp = (__half2*)(g_h + n * DM + lane * 4);
        hp[0] = __floats2half2_rn(hv[0], hv[1]);
        hp[1] = __floats2half2_rn(hv[2], hv[3]);
        int b = n >> 9, j = n & 511;
        ((float4*)out)[(b * 1024 + j) * 32 + lane] =
            make_float4(hv[0], hv[1], hv[2], hv[3]);
    }
    grid_bar(0);

    // ---- binary levels 1..9
#pragma unroll 1
    for (int l = 1; l <= 9; l++) {
        int M      = 32768 >> l;                 // nodes this level
        int s      = 65536 - (65536 >> l);       // level start node
        int Gc     = 65536 - (65536 >> (l - 1)); // child level start
        int cshift = 9 - l;
        int offl   = 1024 - (1024 >> l);
        int czero  = (l == 1);
        int ntile  = ((M + 127) >> 7) << 3;      // m-tiles x 8 d-groups

#pragma unroll 1
        for (int tb = cta; tb < ntile; tb += NC) {
            int m0 = (tb >> 3) * 128;
            int dp = tb & 7;

            __syncthreads();                     // protect sB reuse across tiles
            // stage B: smem row rr = q*16 + d  <-  WT row q*128 + dp*16 + d
#pragma unroll
            for (int it = 0; it < 10; it++) {
                int idx = it * 256 + t;
                int rr = idx >> 5, w = idx & 31;
                int grow = (rr >> 4) * 128 + dp * 16 + (rr & 15);
                *(uint4*)(sB + rr * SBSTR + w * 16) =
                    *(const uint4*)(g_wt + grow * 256 + w * 8);
            }
            __syncthreads();

            const char* A = (const char*)g_h + (size_t)(Gc + 2 * m0) * 256;
            uint32_t arow = (uint32_t)(wid * 16 + g) * 512u + (uint32_t)i * 16u;

            float acc[5][2][4];
#pragma unroll
            for (int q = 0; q < 5; q++)
#pragma unroll
                for (int dh = 0; dh < 2; dh++)
#pragma unroll
                    for (int c = 0; c < 4; c++) acc[q][dh][c] = 0.f;

#pragma unroll
            for (int pr = 0; pr < 8; pr++) {
                uint4 a0 = *(const uint4*)(A + arow + (uint32_t)pr * 64u);
                uint4 a1 = *(const uint4*)(A + arow + 8u * 512u + (uint32_t)pr * 64u);
                uint32_t f0[4] = {a0.x, a1.x, a0.y, a1.y};
                uint32_t f1[4] = {a0.z, a1.z, a0.w, a1.w};
#pragma unroll
                for (int q = 0; q < 5; q++) {
#pragma unroll
                    for (int dh = 0; dh < 2; dh++) {
                        uint4 b = *(const uint4*)(sB + (q * 16 + dh * 8 + g) * SBSTR
                                                  + i * 16 + pr * 64);
                        MMA(acc[q][dh], f0, b.x, b.y);
                        MMA(acc[q][dh], f1, b.z, b.w);
                    }
                }
            }

            // epilogue: thread covers rows {g, g+8} x dims {dh*8 + 2i, +1}
#pragma unroll
            for (int rh = 0; rh < 2; rh++) {
                int lm = wid * 16 + rh * 8 + g;
                if (m0 + lm >= M) continue;
                int node = s + m0 + lm;
                int ch = Gc + 2 * (m0 + lm);
                int local = m0 + lm;
                int b = local >> cshift;
                int jj = local & ((1 << cshift) - 1);
                size_t orow = ((size_t)(b * 1024 + offl + jj)) * DM;
#pragma unroll
                for (int dh = 0; dh < 2; dh++) {
                    int dd = dp * 16 + dh * 8 + i * 2;
                    float2 cl = make_float2(0.f, 0.f), cr = make_float2(0.f, 0.f);
                    if (!czero) {
                        cl = *(const float2*)(g_c + (size_t)ch * DM + dd);
                        cr = *(const float2*)(g_c + (size_t)(ch + 1) * DM + dd);
                    }
                    float hv[2], cv[2];
#pragma unroll
                    for (int e = 0; e < 2; e++) {
                        float gi = acc[0][dh][rh * 2 + e] + bbin[0 * 128 + dd + e];
                        float go = acc[1][dh][rh * 2 + e] + bbin[1 * 128 + dd + e];
                        float gu = acc[2][dh][rh * 2 + e] + bbin[2 * 128 + dd + e];
                        float gl = acc[3][dh][rh * 2 + e] + bbin[3 * 128 + dd + e];
                        float gr = acc[4][dh][rh * 2 + e] + bbin[4 * 128 + dd + e];
                        float clv = e ? cl.y : cl.x;
                        float crv = e ? cr.y : cr.x;
                        float c = sigf(gi) * tanhf(gu) + sigf(gl) * clv + sigf(gr) * crv;
                        cv[e] = c;
                        hv[e] = sigf(go) * tanhf(c);
                    }
                    *(float2*)(g_c + (size_t)node * DM + dd) = make_float2(cv[0], cv[1]);
                    *(__half2*)(g_h + (size_t)node * DM + dd) =
                        __floats2half2_rn(hv[0], hv[1]);
                    *(float2*)(out + orow + dd) = make_float2(hv[0], hv[1]);
                }
            }
        }
        grid_bar(l);
    }

    // ---- unary top level: 64 nodes, child = 65408 + b
    if (cta < 64) {
        float* xh = (float*)sB;
        int ch = 65408 + cta;
        if (t < 128) xh[t] = __half2float(g_h[ch * DM + t]);
        __syncthreads();
        if (t < 128) {
            float acc[4] = {0.f, 0.f, 0.f, 0.f};
            for (int k = 0; k < 128; k++) {
                float x = xh[k];
#pragma unroll
                for (int q = 0; q < 4; q++) acc[q] += x * Wu[k * 512 + q * 128 + t];
            }
            float cc = g_c[ch * DM + t];
            float gi = acc[0] + bu[t];
            float go = acc[1] + bu[128 + t];
            float gu = acc[2] + bu[256 + t];
            float gf = acc[3] + bu[384 + t];
            float c = sigf(gi) * tanhf(gu) + sigf(gf) * cc;
            float h = sigf(go) * tanhf(c);
            out[((size_t)(cta * 1024 + 1023)) * DM + t] = h;
        }
    }
}

// ---------------------------------------------------------------------------
// kernel_launch: ONE kernel launch (graph-capturable, replay-deterministic)
// ---------------------------------------------------------------------------
extern "C" void kernel_launch(void* const* d_in, const int* in_sizes, int n_in,
                              void* d_out, int out_size) {
    const int* tokens = (const int*)d_in[0];
    const float* emb  = (const float*)d_in[3];
    const float* Wu   = (const float*)d_in[4];
    const float* bu   = (const float*)d_in[5];
    const float* Wb   = (const float*)d_in[6];
    const float* bb   = (const float*)d_in[7];
    float* out = (float*)d_out;

    fused<<<NC, 256>>>(tokens, emb, Wu, bu, Wb, bb, out);
}